// round 9
// baseline (speedup 1.0000x reference)
#include <cuda_runtime.h>
#include <stdint.h>

// Shapes (fixed by the problem)
#define B    8
#define C    256
#define HIN  64          // input spatial 64x64
#define S    (HIN*HIN)   // 4096
#define HO   256         // output spatial 256x256
#define K    21
#define EPSF 1e-6f

#define SPLIT  16        // s-range splits for kernD
#define CSPLIT 2         // channel splits (128 c per block) -> 2 CTA/SM
#define SRANGE (S/SPLIT) // 256 s per block
#define SCH    64        // s per smem chunk
#define NCH    (SRANGE/SCH)
#define FSTR   68        // padded row stride (floats): 272B, conflict-free float4
#define CB     (C/CSPLIT)            // 128 channels per block
#define SMEM_D (2*(K*SCH*8 + CB*FSTR*4))   // 2*(10752+34816) = 91136 B

#define SMEM_AB (4*HO*6*8 + 4*K*68*4)      // 49152 + 22848 = 72000 B

// ---------------- scratch (__device__ globals; no allocations) ----------------
__device__ uint64_t g_W2[B * K * S];              // [b][k][s] duplicated (w,w) f32x2 pairs
__device__ unsigned g_rowcnt[B * K * HIN];        // exact 64*count per (b,k,y) row
__device__ float    g_sums[SPLIT * B * K * C];    // partial per-image per-class sums

// bilinear gather weight (in 1/8 units) of input index r from output index Yx
__device__ __forceinline__ int bil_w8(int Yx, int r) {
    int t  = 2 * Yx - 3;
    int y0 = ((t + 8) >> 3) - 1;
    int f8 = (t + 8) & 7;
    int y0c = min(max(y0, 0), HIN - 1);
    int y1c = min(max(y0 + 1, 0), HIN - 1);
    int w = 0;
    if (y0c == r) w += 8 - f8;
    if (y1c == r) w += f8;
    return w;
}

// packed f32x2 helpers (sm_103a FFMA2 via PTX)
__device__ __forceinline__ void fma2(uint64_t& d, uint64_t a, uint64_t b) {
    asm("fma.rn.f32x2 %0, %1, %2, %0;" : "+l"(d) : "l"(a), "l"(b));
}
__device__ __forceinline__ uint64_t add2(uint64_t a, uint64_t b) {
    uint64_t d; asm("add.rn.f32x2 %0, %1, %2;" : "=l"(d) : "l"(a), "l"(b)); return d;
}
__device__ __forceinline__ uint64_t pack2(float x, float y) {
    uint64_t r; asm("mov.b64 %0, {%1, %2};" : "=l"(r) : "f"(x), "f"(y)); return r;
}
__device__ __forceinline__ void unpack2(float& x, float& y, uint64_t a) {
    asm("mov.b64 {%0, %1}, %2;" : "=f"(x), "=f"(y) : "l"(a));
}
// expand 4 bytes -> 4x 16-bit lanes of a u64
__device__ __forceinline__ uint64_t exp16(unsigned v) {
    return (uint64_t)(v & 0xFFu) | ((uint64_t)(v & 0xFF00u) << 8)
         | ((uint64_t)(v & 0xFF0000u) << 16) | ((uint64_t)(v & 0xFF000000u) << 24);
}
// cp.async 16B
__device__ __forceinline__ void cp16(void* dst, const void* src) {
    unsigned u = (unsigned)__cvta_generic_to_shared(dst);
    asm volatile("cp.async.cg.shared.global [%0], [%1], 16;" :: "r"(u), "l"(src));
}

// ---------------- Kernel AB: masks -> W2 (dup pairs) + exact row counts ------
// grid (HIN/4, B), block 256, TWO barriers total.
// P1: thread X=tid builds row-downsampled one-hot T16 for 4 consecutive y rows
//     (16-bit SIMD lanes, 4 classes per u64, 6 words per X).
// P2: thread = (x = tid&63, y = tid>>6): full 8-dx column pass, 6 IMAD.WIDE per
//     dx; per-x result <= 4096 per 16-bit lane (hard bound 64w x 64T). Each
//     thread then emits its 21 W2 dup-pairs (coalesced) and Cs count entries.
// P3: 84 threads sum Cs rows -> g_rowcnt (exact u32, no atomics).
__global__ void kernAB(const int* __restrict__ masks) {
    extern __shared__ unsigned char sm[];
    uint64_t* T16 = (uint64_t*)sm;                    // [4][HO][6]
    unsigned* Cs  = (unsigned*)(sm + 4 * HO * 6 * 8); // [4][K][68]

    int yq = blockIdx.x, b = blockIdx.y;
    int tid = threadIdx.x;

    // P1: 4 y rows, X = tid
    #pragma unroll
    for (int yy = 0; yy < 4; yy++) {
        int y = 4 * yq + yy;
        uint64_t a0 = 0, a1 = 0, a2 = 0;
        #pragma unroll
        for (int dy = 0; dy < 8; dy++) {
            int Y = 4 * y - 2 + dy;
            if (Y < 0 || Y >= HO) continue;
            int w = bil_w8(Y, y);
            if (w == 0) continue;
            int lbl = masks[(b * HO + Y) * HO + tid];
            if ((unsigned)lbl < (unsigned)K) {
                uint64_t add = (uint64_t)w << ((lbl & 7) * 8);
                int sel = lbl >> 3;
                if (sel == 0)      a0 += add;
                else if (sel == 1) a1 += add;
                else               a2 += add;
            }
        }
        uint64_t* Tp = &T16[(yy * HO + tid) * 6];
        Tp[0] = exp16((unsigned)a0); Tp[1] = exp16((unsigned)(a0 >> 32));
        Tp[2] = exp16((unsigned)a1); Tp[3] = exp16((unsigned)(a1 >> 32));
        Tp[4] = exp16((unsigned)a2); Tp[5] = exp16((unsigned)(a2 >> 32));
    }
    __syncthreads();

    // P2: x = tid&63, y = tid>>6 (warp = fixed y, 32 consecutive x)
    {
        int x = tid & 63, yy = tid >> 6;
        int yg = 4 * yq + yy;
        uint64_t acc[6] = {0, 0, 0, 0, 0, 0};
        #pragma unroll
        for (int dx = 0; dx < 8; dx++) {
            int X = 4 * x - 2 + dx;
            if (X < 0 || X >= HO) continue;
            uint64_t w = (uint64_t)(unsigned)bil_w8(X, x);
            if (w == 0) continue;
            const uint64_t* Tp = &T16[(yy * HO + X) * 6];
            #pragma unroll
            for (int j = 0; j < 6; j++) acc[j] += Tp[j] * w;
        }
        // emit 21 classes: W2 dup pairs (coalesced STG.64) + Cs counts
        int s = yg * HIN + x;
        #pragma unroll
        for (int k = 0; k < K; k++) {
            unsigned val = (unsigned)((acc[k >> 2] >> ((k & 3) * 16)) & 0xFFFFull);
            float f = (float)val * (1.0f / 64.0f);
            g_W2[((size_t)b * K + k) * S + s] = pack2(f, f);
            Cs[(yy * K + k) * 68 + x] = val;
        }
    }
    __syncthreads();

    // P3: exact integer row counts
    if (tid < 4 * K) {
        int yy = tid & 3, k = tid >> 2;
        const unsigned* cp = &Cs[(yy * K + k) * 68];
        unsigned t = 0;
        #pragma unroll 16
        for (int xx = 0; xx < HIN; xx++) t += cp[xx];
        g_rowcnt[(b * K + k) * HIN + 4 * yq + yy] = t;
    }
}

// ---------------- Kernel D: sums[sp,b,k,c] = sum_{s in range} feats*W ---------
// grid (SPLIT, CSPLIT, B), block 256 = 8 warps = 2 channel-groups x 4 s-subranges.
// 128 channels per block -> 91 KB smem -> 2 CTAs/SM (barriers & staging hidden).
// lane = channel-pair (c, c+64): W loads are warp-uniform smem broadcasts of
// pre-duplicated (w,w) pairs; fully packed fma.rn.f32x2; cp.async double-buffer.
extern "C" __global__ void __launch_bounds__(256, 2) kernD(const float* __restrict__ feats) {
    extern __shared__ unsigned char smem[];
    uint64_t* Wd = (uint64_t*)smem;                       // [2][K*SCH]
    float*    Fs = (float*)(smem + 2 * K * SCH * 8);      // [2][CB*FSTR]

    int split = blockIdx.x, cb = blockIdx.y, b = blockIdx.z;
    int tid = threadIdx.x, warp = tid >> 5, lane = tid & 31;
    int g = warp & 1, sub = warp >> 1;                    // 2 cgroups x 4 subranges
    int sbase0 = split * SRANGE;

    const float*    Fg  = feats + ((size_t)b * C + cb * CB) * S;
    const uint64_t* Wg2 = &g_W2[(size_t)b * K * S];

    uint64_t acc[K];
    #pragma unroll
    for (int k = 0; k < K; k++) acc[k] = 0ull;

    #define STAGE(BUF, SB) do {                                                   \
        for (int i = tid; i < CB * SCH / 4; i += 256) {                           \
            int c = i >> 4, j4 = i & 15;                                          \
            cp16(&Fs[(BUF) * CB * FSTR + c * FSTR + j4 * 4],                      \
                 Fg + (size_t)c * S + (SB) + j4 * 4);                             \
        }                                                                         \
        for (int i = tid; i < K * SCH / 2; i += 256) {                            \
            int k = i >> 5, j2 = i & 31;                                          \
            cp16(&Wd[(BUF) * K * SCH + k * SCH + j2 * 2],                         \
                 Wg2 + (size_t)k * S + (SB) + j2 * 2);                            \
        }                                                                         \
        asm volatile("cp.async.commit_group;");                                   \
    } while (0)

    STAGE(0, sbase0);

    #pragma unroll 1
    for (int chunk = 0; chunk < NCH; chunk++) {
        if (chunk + 1 < NCH) {
            STAGE((chunk + 1) & 1, sbase0 + (chunk + 1) * SCH);
            asm volatile("cp.async.wait_group 1;");
        } else {
            asm volatile("cp.async.wait_group 0;");
        }
        __syncthreads();

        const float* fA = &Fs[(chunk & 1) * CB * FSTR + (g * 32 + lane) * FSTR];
        const float* fB = fA + 64 * FSTR;
        const uint64_t* Wb = &Wd[(chunk & 1) * K * SCH];
        int sb = sub * 16;
        #pragma unroll
        for (int i = 0; i < 16; i += 4) {
            int s = sb + i;
            float4 va = *(const float4*)&fA[s];
            float4 vb = *(const float4*)&fB[s];
            uint64_t p0 = pack2(va.x, vb.x);
            uint64_t p1 = pack2(va.y, vb.y);
            uint64_t p2 = pack2(va.z, vb.z);
            uint64_t p3 = pack2(va.w, vb.w);
            #pragma unroll
            for (int k = 0; k < K; k++) {
                ulonglong2 w01 = *(const ulonglong2*)&Wb[k * SCH + s];       // broadcast
                ulonglong2 w23 = *(const ulonglong2*)&Wb[k * SCH + s + 2];   // broadcast
                fma2(acc[k], p0, w01.x);
                fma2(acc[k], p1, w01.y);
                fma2(acc[k], p2, w23.x);
                fma2(acc[k], p3, w23.y);
            }
        }
        __syncthreads();   // protect buffer reuse by next prefetch
    }
    #undef STAGE

    // reduce 4 s-subrange warps per channel-group via smem (two steps)
    uint64_t* red = (uint64_t*)smem;   // 2g x 2 x K x 32 u64 = 21504 B (fits)
    if (sub >= 2) {
        #pragma unroll
        for (int k = 0; k < K; k++) red[((g * 2 + (sub - 2)) * K + k) * 32 + lane] = acc[k];
    }
    __syncthreads();
    if (sub < 2) {
        #pragma unroll
        for (int k = 0; k < K; k++) acc[k] = add2(acc[k], red[((g * 2 + sub) * K + k) * 32 + lane]);
    }
    __syncthreads();
    if (sub == 1) {
        #pragma unroll
        for (int k = 0; k < K; k++) red[(g * K + k) * 32 + lane] = acc[k];
    }
    __syncthreads();
    if (sub == 0) {
        float* outp = &g_sums[(((size_t)split * B + b) * K) * C];
        int cg = cb * CB + g * 32 + lane;
        #pragma unroll
        for (int k = 0; k < K; k++) {
            uint64_t t = add2(acc[k], red[(g * K + k) * 32 + lane]);
            float ax, ay;
            unpack2(ax, ay, t);
            outp[k * C + cg]      = ax;
            outp[k * C + cg + 64] = ay;
        }
    }
}

// ---------------- Kernel E: finalize prototypes ------------------------------
// grid (K, 2), block 256 = 8 warps (one per b) x 32 lanes (float4 of channels)
__global__ void kernE(float* __restrict__ out) {
    int k = blockIdx.x, cg = blockIdx.y;
    int tid = threadIdx.x, b = tid >> 5, lane = tid & 31;
    int c4 = cg * 32 + lane;

    const float4* Sp = (const float4*)g_sums;
    float4 v = make_float4(0.f, 0.f, 0.f, 0.f);
    #pragma unroll
    for (int sp = 0; sp < SPLIT; sp++) {
        float4 t = Sp[((sp * B + b) * K + k) * (C / 4) + c4];
        v.x += t.x; v.y += t.y; v.z += t.z; v.w += t.w;
    }
    const unsigned* rc = &g_rowcnt[(b * K + k) * HIN];
    unsigned cr = rc[lane] + rc[lane + 32];
    #pragma unroll
    for (int o = 16; o > 0; o >>= 1) cr += __shfl_xor_sync(0xFFFFFFFFu, cr, o);
    float inv = 1.0f / ((float)cr * (1.0f / 64.0f) + EPSF);
    v.x *= inv; v.y *= inv; v.z *= inv; v.w *= inv;

    __shared__ float4 red[B][32];
    red[b][lane] = v;
    __syncthreads();
    if (b == 0) {
        float4 a = red[0][lane];
        #pragma unroll
        for (int w = 1; w < B; w++) {
            float4 t = red[w][lane];
            a.x += t.x; a.y += t.y; a.z += t.z; a.w += t.w;
        }
        float sc = 1.0f / (float)B;
        a.x *= sc; a.y *= sc; a.z *= sc; a.w *= sc;
        ((float4*)out)[k * (C / 4) + c4] = a;
    }
}

// ---------------- launch -----------------------------------------------------
extern "C" void kernel_launch(void* const* d_in, const int* in_sizes, int n_in,
                              void* d_out, int out_size) {
    const float* feats = (const float*)d_in[0];   // [8,256,64,64]
    const int*   masks = (const int*)d_in[1];     // [8,256,256]
    float*       out   = (float*)d_out;           // [21,256]

    cudaFuncSetAttribute(kernAB, cudaFuncAttributeMaxDynamicSharedMemorySize, SMEM_AB);
    cudaFuncSetAttribute(kernD,  cudaFuncAttributeMaxDynamicSharedMemorySize, SMEM_D);

    kernAB<<<dim3(HIN / 4, B), 256, SMEM_AB>>>(masks);
    kernD<<<dim3(SPLIT, CSPLIT, B), 256, SMEM_D>>>(feats);
    kernE<<<dim3(K, 2), 256>>>(out);
}